// round 10
// baseline (speedup 1.0000x reference)
#include <cuda_runtime.h>
#include <cuda_fp16.h>
#include <stdint.h>

// Problem constants
constexpr int kB  = 4;
constexpr int kH  = 8;
constexpr int kNQ = 1024;
constexpr int kNC = 8192;
constexpr int kD  = 512;
constexpr int kHD = 64;
constexpr int kSplits = 4;
constexpr int kRows = kB * kH * kNQ;   // 32768 (bh*nq rows)

// Q pre-scale: 1/sqrt(64) * log2(e)  (softmax computed with exp2)
constexpr float kQScale = 0.18033688011112042f;

// Scratch (allocation is forbidden; use device globals)
__device__ __align__(16) __half g_qh[kB * kH * kNQ * kHD];    //  4 MB scaled fp16
__device__ __align__(16) __half g_kh[kB * kH * kNC * kHD];    // 32 MB fp16
__device__ __align__(16) __half g_vh[kB * kH * kNC * kHD];    // 32 MB fp16
__device__ __align__(16) __half g_oh[kB * kNQ * kD];          //  4 MB fp16 [b,nq,h*64]
__device__ __align__(16) float  g_po[kSplits * kRows * kHD];  // 32 MB unnormalized O partials
__device__ __align__(16) float  g_pl[kSplits * kRows];        // 512 KB l partials

// ---------------------------------------------------------------------------
// Helpers
// ---------------------------------------------------------------------------
__device__ __forceinline__ uint32_t smem_u32(const void* p) {
    uint32_t a;
    asm("{ .reg .u64 t; cvta.to.shared.u64 t, %1; cvt.u32.u64 %0, t; }"
        : "=r"(a) : "l"(p));
    return a;
}
#define CP16(dst_u32, src_ptr) \
    asm volatile("cp.async.cg.shared.global [%0], [%1], 16;" \
                 :: "r"(dst_u32), "l"(src_ptr) : "memory")
#define CP_COMMIT() asm volatile("cp.async.commit_group;" ::: "memory")
#define CP_WAIT0()  asm volatile("cp.async.wait_group 0;" ::: "memory")

#define LDSM4(r, addr) \
    asm volatile("ldmatrix.sync.aligned.m8n8.x4.shared.b16 {%0,%1,%2,%3}, [%4];" \
                 : "=r"((r)[0]), "=r"((r)[1]), "=r"((r)[2]), "=r"((r)[3]) : "r"(addr))
#define LDSM4T(r, addr) \
    asm volatile("ldmatrix.sync.aligned.m8n8.x4.trans.shared.b16 {%0,%1,%2,%3}, [%4];" \
                 : "=r"((r)[0]), "=r"((r)[1]), "=r"((r)[2]), "=r"((r)[3]) : "r"(addr))

// m16n8k16 fp16 mma, fp32 accumulate.
__device__ __forceinline__ void mma_f16(float d[4], const uint32_t a[4],
                                        uint32_t b0, uint32_t b1)
{
    asm volatile(
        "mma.sync.aligned.m16n8k16.row.col.f32.f16.f16.f32 "
        "{%0,%1,%2,%3}, {%4,%5,%6,%7}, {%8,%9}, {%0,%1,%2,%3};"
        : "+f"(d[0]), "+f"(d[1]), "+f"(d[2]), "+f"(d[3])
        : "r"(a[0]), "r"(a[1]), "r"(a[2]), "r"(a[3]), "r"(b0), "r"(b1));
}

// m16n8k16 fp16 mma, fp16 accumulate (D/C are 2 x u32 = 4 halves).
__device__ __forceinline__ void mma_f16acc(uint32_t d[2], const uint32_t a[4],
                                           uint32_t b0, uint32_t b1)
{
    asm volatile(
        "mma.sync.aligned.m16n8k16.row.col.f16.f16.f16.f16 "
        "{%0,%1}, {%2,%3,%4,%5}, {%6,%7}, {%0,%1};"
        : "+r"(d[0]), "+r"(d[1])
        : "r"(a[0]), "r"(a[1]), "r"(a[2]), "r"(a[3]), "r"(b0), "r"(b1));
}

// 2^x on packed f16x2 (direct on mma f16 accumulator registers)
__device__ __forceinline__ uint32_t ex2u(uint32_t u) {
    uint32_t r;
    asm("ex2.approx.f16x2 %0, %1;" : "=r"(r) : "r"(u));
    return r;
}

// pack 2 float4 (8 floats) -> 8 halves into dst
__device__ __forceinline__ void pack8(__half* dst, const float4& u, const float4& v) {
    __half2 h[4];
    h[0] = __floats2half2_rn(u.x, u.y);
    h[1] = __floats2half2_rn(u.z, u.w);
    h[2] = __floats2half2_rn(v.x, v.y);
    h[3] = __floats2half2_rn(v.z, v.w);
    *(uint4*)dst = *(uint4*)h;
}

// ---------------------------------------------------------------------------
// Unified fp16 tensor GEMM, CTA tile 128x128, 8 warps 2m x 4n, K chunks of 32,
// double-buffered smem. MODE 1 uses swapped grid (n fastest) for ctx L2 reuse.
// MODE 0: q-proj  A=x(fp32)      B=Wq   -> g_qh (scaled fp16 scatter)
// MODE 1: kv-proj A=ctx(fp32)    B=Wkv  -> g_kh/g_vh (fp16 scatter)
// MODE 2: out-proj A=g_oh(fp16)  B=Wout -> Cout fp32 (+bias)
// ---------------------------------------------------------------------------
template <int MODE>
__global__ __launch_bounds__(256) void hgemm(
    const float* __restrict__ Af, const float* __restrict__ Bm,
    const float* __restrict__ bias, float* __restrict__ Cout)
{
    constexpr int N = (MODE == 1) ? 1024 : 512;
    __shared__ __align__(16) __half As[2][128 * 40];
    __shared__ __align__(16) __half Bs[2][32 * 136];

    const int tid = threadIdx.x, lane = tid & 31, wid = tid >> 5;
    const int g = lane >> 2, tq2 = (lane & 3) << 1;
    const int m0 = (MODE == 1 ? blockIdx.y : blockIdx.x) << 7;
    const int n0 = (MODE == 1 ? blockIdx.x : blockIdx.y) << 7;
    const int arow = (wid >> 2) << 6, bcol = (wid & 3) << 5;

    const int aR = tid >> 1, aK = (tid & 1) << 4;   // A: 2 thr/row, 16 elems each
    const int bK = tid >> 3, bN = (tid & 7) << 4;   // B: 8 thr/row, 16 n each

    const int arow_l = (lane & 7) + ((lane >> 3) & 1) * 8;
    const int acol_l = ((lane >> 4) & 1) * 8;
    const int brow_l = (lane & 7) + ((lane >> 3) & 1) * 8;
    const int bcol_l = ((lane >> 4) & 1) * 8;

    float4 pa[4], pb[4];
    uint4 pa16[2];
#pragma unroll
    for (int p = 0; p < 4; p++)
        pb[p] = *(const float4*)(Bm + (size_t)bK * N + n0 + bN + (p << 2));
    if (MODE == 2) {
        const __half* Ah = g_oh + (size_t)(m0 + aR) * kD + aK;
        pa16[0] = *(const uint4*)Ah;
        pa16[1] = *(const uint4*)(Ah + 8);
    } else {
#pragma unroll
        for (int p = 0; p < 4; p++)
            pa[p] = *(const float4*)(Af + (size_t)(m0 + aR) * kD + aK + (p << 2));
    }

    // stage chunk 0 into buffer 0
    if (MODE == 2) {
        *(uint4*)(As[0] + aR * 40 + aK) = pa16[0];
        *(uint4*)(As[0] + aR * 40 + aK + 8) = pa16[1];
    } else {
        pack8(As[0] + aR * 40 + aK,     pa[0], pa[1]);
        pack8(As[0] + aR * 40 + aK + 8, pa[2], pa[3]);
    }
    pack8(Bs[0] + bK * 136 + bN,     pb[0], pb[1]);
    pack8(Bs[0] + bK * 136 + bN + 8, pb[2], pb[3]);
    __syncthreads();

    float acc[4][4][4] = {};

    for (int c = 0; c < 16; c++) {
        const int cur = c & 1;
        if (c < 15) {
            const int k0 = (c + 1) << 5;
#pragma unroll
            for (int p = 0; p < 4; p++)
                pb[p] = *(const float4*)(Bm + (size_t)(k0 + bK) * N + n0 + bN + (p << 2));
            if (MODE == 2) {
                const __half* Ah = g_oh + (size_t)(m0 + aR) * kD + k0 + aK;
                pa16[0] = *(const uint4*)Ah;
                pa16[1] = *(const uint4*)(Ah + 8);
            } else {
#pragma unroll
                for (int p = 0; p < 4; p++)
                    pa[p] = *(const float4*)(Af + (size_t)(m0 + aR) * kD + k0 + aK + (p << 2));
            }
        }
        const uint32_t asb = smem_u32(As[cur]), bsb = smem_u32(Bs[cur]);
#pragma unroll
        for (int h16 = 0; h16 < 2; h16++) {
            uint32_t a[4][4];
#pragma unroll
            for (int mf = 0; mf < 4; mf++)
                LDSM4(a[mf], asb + 2 * ((arow + (mf << 4) + arow_l) * 40 + (h16 << 4) + acol_l));
#pragma unroll
            for (int np = 0; np < 2; np++) {
                uint32_t b[4];
                LDSM4T(b, bsb + 2 * (((h16 << 4) + brow_l) * 136 + bcol + (np << 4) + bcol_l));
#pragma unroll
                for (int mf = 0; mf < 4; mf++) {
                    mma_f16(acc[mf][2 * np + 0], a[mf], b[0], b[1]);
                    mma_f16(acc[mf][2 * np + 1], a[mf], b[2], b[3]);
                }
            }
        }
        if (c < 15) {
            const int nxt = 1 - cur;
            if (MODE == 2) {
                *(uint4*)(As[nxt] + aR * 40 + aK) = pa16[0];
                *(uint4*)(As[nxt] + aR * 40 + aK + 8) = pa16[1];
            } else {
                pack8(As[nxt] + aR * 40 + aK,     pa[0], pa[1]);
                pack8(As[nxt] + aR * 40 + aK + 8, pa[2], pa[3]);
            }
            pack8(Bs[nxt] + bK * 136 + bN,     pb[0], pb[1]);
            pack8(Bs[nxt] + bK * 136 + bN + 8, pb[2], pb[3]);
        }
        __syncthreads();
    }

    // Epilogues
#pragma unroll
    for (int mf = 0; mf < 4; mf++) {
        const int m = m0 + arow + (mf << 4) + g;
#pragma unroll
        for (int nf = 0; nf < 4; nf++) {
            const int n = n0 + bcol + (nf << 3) + tq2;
            if (MODE == 0) {
                const int b_idx = m >> 10, iq = m & 1023;
                const int h = n >> 6, d = n & 63;
                __half* p0 = g_qh + (((size_t)(b_idx * kH + h) * kNQ + iq) << 6) + d;
                *(__half2*)p0 = __floats2half2_rn(acc[mf][nf][0] * kQScale,
                                                  acc[mf][nf][1] * kQScale);
                *(__half2*)(p0 + 512) = __floats2half2_rn(acc[mf][nf][2] * kQScale,
                                                          acc[mf][nf][3] * kQScale);
            } else if (MODE == 1) {
                const int bi = m >> 13, ic = m & 8191;
                __half* dst = (n < kD) ? g_kh : g_vh;
                const int h = (n >> 6) & 7, d = n & 63;
                __half* p0 = dst + (((size_t)(bi * kH + h) * kNC + ic) << 6) + d;
                *(__half2*)p0 = __floats2half2_rn(acc[mf][nf][0], acc[mf][nf][1]);
                *(__half2*)(p0 + 512) = __floats2half2_rn(acc[mf][nf][2], acc[mf][nf][3]);
            } else {
                const float b0 = bias[n], b1 = bias[n + 1];
                *(float2*)(Cout + (size_t)m * kD + n) =
                    make_float2(acc[mf][nf][0] + b0, acc[mf][nf][1] + b1);
                *(float2*)(Cout + (size_t)(m + 8) * kD + n) =
                    make_float2(acc[mf][nf][2] + b0, acc[mf][nf][3] + b1);
            }
        }
    }
}

// ---------------------------------------------------------------------------
// Flash attention, split-KV. CTA = (q-tile 256, bh, split); 256 thr / 8 warps;
// warp owns 32 q-rows x full 64 kv/d. Split = 2048 kv (32 tiles).
// S = QK^T with fp16 accumulators -> ex2.f16x2 directly on D-frags -> PV A-frags.
// O/l partials fp32, unnormalized; combine kernel reduces over splits.
// ---------------------------------------------------------------------------
constexpr int H_K0 = 0;
constexpr int H_V0 = 4608;
constexpr int H_K1 = 9216;
constexpr int H_V1 = 13824;
constexpr int AT_SMEM = 18432 * 2;   // 36864 bytes
constexpr uint32_t ONES = 0x3C003C00u;  // half2(1.0, 1.0)
constexpr int kTilesPerSplit = kNC / 64 / kSplits;   // 32
constexpr int kQTile = 256;

__global__ __launch_bounds__(256) void attn_mma()
{
    extern __shared__ __align__(16) __half sh[];
    const uint32_t sb = smem_u32(sh);

    const int tid = threadIdx.x, lane = tid & 31, wid = tid >> 5;
    const int g = lane >> 2, tq2 = (lane & 3) << 1;
    const int wr = wid << 5;                      // warp q-row base within 256-tile
    const int bh = blockIdx.y, q0 = blockIdx.x << 8, sp = blockIdx.z;
    const int t0 = sp * kTilesPerSplit;

    const __half* Qg = g_qh + ((size_t)bh * kNQ + q0) * kHD;
    const __half* Kg = g_kh + (size_t)bh * kNC * kHD + (size_t)t0 * 64 * kHD;
    const __half* Vg = g_vh + (size_t)bh * kNC * kHD + (size_t)t0 * 64 * kHD;

    // ldmatrix lane offsets
    const int qrow_l = (lane & 7) + ((lane >> 3) & 1) * 8;   // V source rows (trans)
    const int qcol_l = ((lane >> 4) & 1) * 8;
    const int krow_l = (lane & 7) + ((lane >> 4) & 1) * 8;   // K (B) n-rows
    const int kcol_l = ((lane >> 3) & 1) * 8;

    // Stage K/V tile 0 (512 x 16B each, 256 threads -> 2+2 per thread)
#pragma unroll
    for (int p = 0; p < 2; p++) {
        int c = tid + (p << 8);
        int row = c >> 3, seg = (c & 7) << 3;
        CP16(sb + 2 * (H_K0 + row * 72 + seg), Kg + (row << 6) + seg);
        CP16(sb + 2 * (H_V0 + row * 72 + seg), Vg + (row << 6) + seg);
    }
    CP_COMMIT();

    // Q fragments straight from gmem (once per CTA)
    uint32_t qa[2][4][4];
#pragma unroll
    for (int mf = 0; mf < 2; mf++)
#pragma unroll
        for (int kc = 0; kc < 4; kc++) {
            const __half* qp = Qg + (wr + (mf << 4) + g) * kHD + (kc << 4) + tq2;
            qa[mf][kc][0] = *(const uint32_t*)qp;
            qa[mf][kc][1] = *(const uint32_t*)(qp + 8 * kHD);
            qa[mf][kc][2] = *(const uint32_t*)(qp + 8);
            qa[mf][kc][3] = *(const uint32_t*)(qp + 8 * kHD + 8);
        }

    float o[2][8][4] = {};
    float ol[2][4] = {};

    CP_WAIT0();
    __syncthreads();

    for (int tk = 0; tk < kTilesPerSplit; tk++) {
        const int cur = tk & 1;
        if (tk < kTilesPerSplit - 1) {
            const __half* Kt = Kg + (size_t)(tk + 1) * 64 * kHD;
            const __half* Vt = Vg + (size_t)(tk + 1) * 64 * kHD;
            const int kd = cur ? H_K0 : H_K1;
            const int vd = cur ? H_V0 : H_V1;
#pragma unroll
            for (int p = 0; p < 2; p++) {
                int c = tid + (p << 8);
                int row = c >> 3, seg = (c & 7) << 3;
                CP16(sb + 2 * (kd + row * 72 + seg), Kt + (row << 6) + seg);
                CP16(sb + 2 * (vd + row * 72 + seg), Vt + (row << 6) + seg);
            }
            CP_COMMIT();
        }
        const uint32_t kbase = sb + 2 * (cur ? H_K1 : H_K0);
        const uint32_t vbase = sb + 2 * (cur ? H_V1 : H_V0);

#pragma unroll
        for (int np = 0; np < 4; np++) {
            // ---- S = Q.K^T (fp16 accumulate) for kv cols 16np..+15 ----
            uint32_t s[2][2][2] = {};   // [mf][j][reg] packed half2
#pragma unroll
            for (int kc = 0; kc < 4; kc++) {
                uint32_t kb[4];
                LDSM4(kb, kbase + 2 * (((np << 4) + krow_l) * 72 + (kc << 4) + kcol_l));
                mma_f16acc(s[0][0], qa[0][kc], kb[0], kb[1]);
                mma_f16acc(s[1][0], qa[1][kc], kb[0], kb[1]);
                mma_f16acc(s[0][1], qa[0][kc], kb[2], kb[3]);
                mma_f16acc(s[1][1], qa[1][kc], kb[2], kb[3]);
            }
            // ---- exp2 directly on f16x2 accumulators -> PV A-frags ----
            uint32_t pa[2][4];
#pragma unroll
            for (int mf = 0; mf < 2; mf++) {
                pa[mf][0] = ex2u(s[mf][0][0]);
                pa[mf][1] = ex2u(s[mf][0][1]);
                pa[mf][2] = ex2u(s[mf][1][0]);
                pa[mf][3] = ex2u(s[mf][1][1]);
            }
            // ---- O += P.V (kv chunk np), l += P.1 ----
#pragma unroll
            for (int vc = 0; vc < 4; vc++) {
                uint32_t vb[4];
                LDSM4T(vb, vbase + 2 * (((np << 4) + qrow_l) * 72 + (vc << 4) + qcol_l));
                mma_f16(o[0][(vc << 1) + 0], pa[0], vb[0], vb[1]);
                mma_f16(o[1][(vc << 1) + 0], pa[1], vb[0], vb[1]);
                mma_f16(o[0][(vc << 1) + 1], pa[0], vb[2], vb[3]);
                mma_f16(o[1][(vc << 1) + 1], pa[1], vb[2], vb[3]);
            }
            mma_f16(ol[0], pa[0], ONES, ONES);
            mma_f16(ol[1], pa[1], ONES, ONES);
        }

        if (tk < kTilesPerSplit - 1) {
            CP_WAIT0();
            __syncthreads();
        }
    }

    // store unnormalized partials
    float* pbase = g_po + ((size_t)sp * kRows + (size_t)bh * kNQ + q0) * kHD;
#pragma unroll
    for (int mf = 0; mf < 2; mf++) {
        const int r0 = wr + (mf << 4) + g;
        float* rp = pbase + r0 * kHD;
#pragma unroll
        for (int nf = 0; nf < 8; nf++) {
            const int d = (nf << 3) + tq2;
            *(float2*)(rp + d) = make_float2(o[mf][nf][0], o[mf][nf][1]);
            *(float2*)(rp + 8 * kHD + d) = make_float2(o[mf][nf][2], o[mf][nf][3]);
        }
        if ((lane & 3) == 0) {
            g_pl[(size_t)sp * kRows + (size_t)bh * kNQ + q0 + r0] = ol[mf][0];
            g_pl[(size_t)sp * kRows + (size_t)bh * kNQ + q0 + r0 + 8] = ol[mf][2];
        }
    }
}

// ---------------------------------------------------------------------------
// Combine: sum split partials, normalize, write fp16 g_oh [b,nq,h*64+d]
// ---------------------------------------------------------------------------
__global__ __launch_bounds__(256) void combine_kernel()
{
    const int idx = blockIdx.x * 256 + threadIdx.x;   // 524288 threads
    const int row = idx >> 4;                          // bh*1024 + iq
    const int d4 = (idx & 15) << 2;

    float4 acc = make_float4(0.f, 0.f, 0.f, 0.f);
    float l = 0.f;
#pragma unroll
    for (int s = 0; s < kSplits; s++) {
        const float4 v = *(const float4*)(g_po + ((size_t)s * kRows + row) * kHD + d4);
        acc.x += v.x; acc.y += v.y; acc.z += v.z; acc.w += v.w;
        l += g_pl[(size_t)s * kRows + row];
    }
    const float inv = 1.0f / l;
    const int bh = row >> 10, iq = row & 1023;
    const int b = bh >> 3, h = bh & 7;
    __half2 h0 = __floats2half2_rn(acc.x * inv, acc.y * inv);
    __half2 h1 = __floats2half2_rn(acc.z * inv, acc.w * inv);
    __half* dst = g_oh + ((size_t)(b * kNQ) + iq) * kD + (h << 6) + d4;
    uint2 u;
    u.x = *(uint32_t*)&h0; u.y = *(uint32_t*)&h1;
    *(uint2*)dst = u;
}

// ---------------------------------------------------------------------------
extern "C" void kernel_launch(void* const* d_in, const int* in_sizes, int n_in,
                              void* d_out, int out_size)
{
    const float* x    = (const float*)d_in[0];
    const float* ctx  = (const float*)d_in[1];
    const float* Wq   = (const float*)d_in[2];
    const float* Wkv  = (const float*)d_in[3];
    const float* Wout = (const float*)d_in[4];
    const float* bout = (const float*)d_in[5];
    float* out = (float*)d_out;

    cudaFuncSetAttribute(attn_mma, cudaFuncAttributeMaxDynamicSharedMemorySize, AT_SMEM);

    // q = x @ Wq (fp16 mma, scale epilogue) -> g_qh
    hgemm<0><<<dim3(32, 4), 256>>>(x, Wq, nullptr, nullptr);
    // kv = context @ Wkv (fp16 mma, n-fastest grid for ctx L2 reuse) -> g_kh, g_vh
    hgemm<1><<<dim3(8, 256), 256>>>(ctx, Wkv, nullptr, nullptr);
    // flash attention split-KV (q-tile 256) -> g_po, g_pl
    attn_mma<<<dim3(kNQ / kQTile, 32, kSplits), 256, AT_SMEM>>>();
    // combine partials -> g_oh
    combine_kernel<<<2048, 256>>>();
    // out = g_oh @ Wout + bout (fp16 mma, fp32 out)
    hgemm<2><<<dim3(32, 4), 256>>>(nullptr, Wout, bout, out);
}

// round 12
// speedup vs baseline: 1.2519x; 1.2519x over previous
#include <cuda_runtime.h>
#include <cuda_fp16.h>
#include <stdint.h>

// Problem constants
constexpr int kB  = 4;
constexpr int kH  = 8;
constexpr int kNQ = 1024;
constexpr int kNC = 8192;
constexpr int kD  = 512;
constexpr int kHD = 64;
constexpr int kSplits = 4;
constexpr int kRows = kB * kH * kNQ;   // 32768

// Q pre-scale: 1/sqrt(64) * log2(e)
constexpr float kQScale = 0.18033688011112042f;

// Scratch (allocation is forbidden; use device globals)
__device__ __align__(16) __half g_xh  [kB * kNQ * kD];        //  4 MB fp16 x
__device__ __align__(16) __half g_ctxh[kB * kNC * kD];        // 32 MB fp16 context
__device__ __align__(16) __half g_wqh [kD * kD];              // fp16 Wq
__device__ __align__(16) __half g_wkvh[kD * 2 * kD];          // fp16 Wkv
__device__ __align__(16) __half g_wouth[kD * kD];             // fp16 Wout
__device__ __align__(16) __half g_qh[kB * kH * kNQ * kHD];    //  4 MB scaled fp16 q
__device__ __align__(16) __half g_kh[kB * kH * kNC * kHD];    // 32 MB fp16 k
__device__ __align__(16) __half g_vh[kB * kH * kNC * kHD];    // 32 MB fp16 v
__device__ __align__(16) __half g_oh[kB * kNQ * kD];          //  4 MB fp16 attn out
__device__ __align__(16) float  g_po[kSplits * kRows * kHD];  // 32 MB O partials
__device__ __align__(16) float  g_pl[kSplits * kRows];        // l partials

// ---------------------------------------------------------------------------
// Helpers
// ---------------------------------------------------------------------------
__device__ __forceinline__ uint32_t smem_u32(const void* p) {
    uint32_t a;
    asm("{ .reg .u64 t; cvta.to.shared.u64 t, %1; cvt.u32.u64 %0, t; }"
        : "=r"(a) : "l"(p));
    return a;
}
#define CP16(dst_u32, src_ptr) \
    asm volatile("cp.async.cg.shared.global [%0], [%1], 16;" \
                 :: "r"(dst_u32), "l"(src_ptr) : "memory")
#define CP_COMMIT() asm volatile("cp.async.commit_group;" ::: "memory")
#define CP_WAIT0()  asm volatile("cp.async.wait_group 0;" ::: "memory")

#define LDSM4(r, addr) \
    asm volatile("ldmatrix.sync.aligned.m8n8.x4.shared.b16 {%0,%1,%2,%3}, [%4];" \
                 : "=r"((r)[0]), "=r"((r)[1]), "=r"((r)[2]), "=r"((r)[3]) : "r"(addr))
#define LDSM4T(r, addr) \
    asm volatile("ldmatrix.sync.aligned.m8n8.x4.trans.shared.b16 {%0,%1,%2,%3}, [%4];" \
                 : "=r"((r)[0]), "=r"((r)[1]), "=r"((r)[2]), "=r"((r)[3]) : "r"(addr))

// m16n8k16 fp16 mma, fp32 accumulate.
__device__ __forceinline__ void mma_f16(float d[4], const uint32_t a[4],
                                        uint32_t b0, uint32_t b1)
{
    asm volatile(
        "mma.sync.aligned.m16n8k16.row.col.f32.f16.f16.f32 "
        "{%0,%1,%2,%3}, {%4,%5,%6,%7}, {%8,%9}, {%0,%1,%2,%3};"
        : "+f"(d[0]), "+f"(d[1]), "+f"(d[2]), "+f"(d[3])
        : "r"(a[0]), "r"(a[1]), "r"(a[2]), "r"(a[3]), "r"(b0), "r"(b1));
}

// m16n8k16 fp16 mma, fp16 accumulate; d points at 2 u32 (4 halves).
__device__ __forceinline__ void mma_f16acc(uint32_t* d, const uint32_t a[4],
                                           uint32_t b0, uint32_t b1)
{
    asm volatile(
        "mma.sync.aligned.m16n8k16.row.col.f16.f16.f16.f16 "
        "{%0,%1}, {%2,%3,%4,%5}, {%6,%7}, {%0,%1};"
        : "+r"(d[0]), "+r"(d[1])
        : "r"(a[0]), "r"(a[1]), "r"(a[2]), "r"(a[3]), "r"(b0), "r"(b1));
}

// 2^x on packed f16x2
__device__ __forceinline__ uint32_t ex2u(uint32_t u) {
    uint32_t r;
    asm("ex2.approx.f16x2 %0, %1;" : "=r"(r) : "r"(u));
    return r;
}
__device__ __forceinline__ uint32_t hadd2u(uint32_t a, uint32_t b) {
    uint32_t r;
    asm("add.f16x2 %0, %1, %2;" : "=r"(r) : "r"(a), "r"(b));
    return r;
}

// ---------------------------------------------------------------------------
// fp32 -> fp16 bulk convert (8 elems / thread)
// ---------------------------------------------------------------------------
__global__ __launch_bounds__(256) void cvt_f2h(
    const float* __restrict__ src, __half* __restrict__ dst, int n8)
{
    const int i = blockIdx.x * 256 + threadIdx.x;
    if (i >= n8) return;
    float4 a = *(const float4*)(src + (size_t)i * 8);
    float4 b = *(const float4*)(src + (size_t)i * 8 + 4);
    __half2 h[4];
    h[0] = __floats2half2_rn(a.x, a.y);
    h[1] = __floats2half2_rn(a.z, a.w);
    h[2] = __floats2half2_rn(b.x, b.y);
    h[3] = __floats2half2_rn(b.z, b.w);
    *(uint4*)(dst + (size_t)i * 8) = *(uint4*)h;
}

// ---------------------------------------------------------------------------
// Pure-fp16 tensor GEMM, CTA 128x128, 8 warps 2m x 4n, K chunks of 32,
// cp.async double-buffered staging (A and B already fp16 in gmem).
// MODE 0: A=g_xh    B=g_wqh   -> g_qh (scaled fp16 scatter)
// MODE 1: A=g_ctxh  B=g_wkvh  -> g_kh/g_vh (fp16 scatter); grid n-fastest
// MODE 2: A=g_oh    B=g_wouth -> Cout fp32 (+bias)
// ---------------------------------------------------------------------------
template <int MODE>
__global__ __launch_bounds__(256) void hgemm(
    const __half* __restrict__ Ah, const __half* __restrict__ Bh,
    const float* __restrict__ bias, float* __restrict__ Cout)
{
    constexpr int N = (MODE == 1) ? 1024 : 512;
    __shared__ __align__(16) __half As[2][128 * 40];
    __shared__ __align__(16) __half Bs[2][32 * 136];

    const int tid = threadIdx.x, lane = tid & 31, wid = tid >> 5;
    const int g = lane >> 2, tq2 = (lane & 3) << 1;
    const int m0 = (MODE == 1 ? blockIdx.y : blockIdx.x) << 7;
    const int n0 = (MODE == 1 ? blockIdx.x : blockIdx.y) << 7;
    const int arow = (wid >> 2) << 6, bcol = (wid & 3) << 5;

    const uint32_t asb0 = smem_u32(As[0]), bsb0 = smem_u32(Bs[0]);
    const uint32_t asb1 = smem_u32(As[1]), bsb1 = smem_u32(Bs[1]);

    const int arow_l = (lane & 7) + ((lane >> 3) & 1) * 8;
    const int acol_l = ((lane >> 4) & 1) * 8;
    const int brow_l = (lane & 7) + ((lane >> 3) & 1) * 8;
    const int bcol_l = ((lane >> 4) & 1) * 8;

    // staging: 2 A-segs + 2 B-segs per thread per chunk
    const int ia0 = tid << 1;
    const int aR0 = ia0 >> 2,  aO0 = (ia0 & 3) << 3;
    const int aR1 = (ia0 + 1) >> 2, aO1 = ((ia0 + 1) & 3) << 3;
    const int bR0 = ia0 >> 4,  bO0 = (ia0 & 15) << 3;
    const int bR1 = (ia0 + 1) >> 4, bO1 = ((ia0 + 1) & 15) << 3;

    auto stage = [&](uint32_t ab, uint32_t bb, int k0) {
        CP16(ab + 2 * (aR0 * 40 + aO0), Ah + (size_t)(m0 + aR0) * kD + k0 + aO0);
        CP16(ab + 2 * (aR1 * 40 + aO1), Ah + (size_t)(m0 + aR1) * kD + k0 + aO1);
        CP16(bb + 2 * (bR0 * 136 + bO0), Bh + (size_t)(k0 + bR0) * N + n0 + bO0);
        CP16(bb + 2 * (bR1 * 136 + bO1), Bh + (size_t)(k0 + bR1) * N + n0 + bO1);
        CP_COMMIT();
    };

    stage(asb0, bsb0, 0);

    float acc[4][4][4] = {};

    for (int c = 0; c < 16; c++) {
        const int cur = c & 1;
        CP_WAIT0();
        __syncthreads();
        if (c < 15)
            stage(cur ? asb0 : asb1, cur ? bsb0 : bsb1, (c + 1) << 5);
        const uint32_t asb = cur ? asb1 : asb0;
        const uint32_t bsb = cur ? bsb1 : bsb0;
#pragma unroll
        for (int h16 = 0; h16 < 2; h16++) {
            uint32_t a[4][4];
#pragma unroll
            for (int mf = 0; mf < 4; mf++)
                LDSM4(a[mf], asb + 2 * ((arow + (mf << 4) + arow_l) * 40 + (h16 << 4) + acol_l));
#pragma unroll
            for (int np = 0; np < 2; np++) {
                uint32_t b[4];
                LDSM4T(b, bsb + 2 * (((h16 << 4) + brow_l) * 136 + bcol + (np << 4) + bcol_l));
#pragma unroll
                for (int mf = 0; mf < 4; mf++) {
                    mma_f16(acc[mf][2 * np + 0], a[mf], b[0], b[1]);
                    mma_f16(acc[mf][2 * np + 1], a[mf], b[2], b[3]);
                }
            }
        }
    }

    // Epilogues
#pragma unroll
    for (int mf = 0; mf < 4; mf++) {
        const int m = m0 + arow + (mf << 4) + g;
#pragma unroll
        for (int nf = 0; nf < 4; nf++) {
            const int n = n0 + bcol + (nf << 3) + tq2;
            if (MODE == 0) {
                const int b_idx = m >> 10, iq = m & 1023;
                const int h = n >> 6, d = n & 63;
                __half* p0 = g_qh + (((size_t)(b_idx * kH + h) * kNQ + iq) << 6) + d;
                *(__half2*)p0 = __floats2half2_rn(acc[mf][nf][0] * kQScale,
                                                  acc[mf][nf][1] * kQScale);
                *(__half2*)(p0 + 512) = __floats2half2_rn(acc[mf][nf][2] * kQScale,
                                                          acc[mf][nf][3] * kQScale);
            } else if (MODE == 1) {
                const int bi = m >> 13, ic = m & 8191;
                __half* dst = (n < kD) ? g_kh : g_vh;
                const int h = (n >> 6) & 7, d = n & 63;
                __half* p0 = dst + (((size_t)(bi * kH + h) * kNC + ic) << 6) + d;
                *(__half2*)p0 = __floats2half2_rn(acc[mf][nf][0], acc[mf][nf][1]);
                *(__half2*)(p0 + 512) = __floats2half2_rn(acc[mf][nf][2], acc[mf][nf][3]);
            } else {
                const float b0 = bias[n], b1 = bias[n + 1];
                *(float2*)(Cout + (size_t)m * kD + n) =
                    make_float2(acc[mf][nf][0] + b0, acc[mf][nf][1] + b1);
                *(float2*)(Cout + (size_t)(m + 8) * kD + n) =
                    make_float2(acc[mf][nf][2] + b0, acc[mf][nf][3] + b1);
            }
        }
    }
}

// ---------------------------------------------------------------------------
// Flash attention, split-KV, phase-batched. CTA = (128-q tile, bh, split);
// 128 thr / 4 warps; warp owns 32 q-rows x 64 kv/d. Per kv tile:
//   [all-S: 64 f16acc mma] -> [all-ex2: 32 f16x2] -> [all-PV: 64 f32acc mma]
// l via HADD2 trees on P frags (off the tensor pipe), f32 accumulation.
// ---------------------------------------------------------------------------
constexpr int H_K0 = 0;
constexpr int H_V0 = 4608;
constexpr int H_K1 = 9216;
constexpr int H_V1 = 13824;
constexpr int AT_SMEM = 18432 * 2;   // 36864 bytes
constexpr int kTilesPerSplit = kNC / 64 / kSplits;   // 32

__global__ __launch_bounds__(128) void attn_mma()
{
    extern __shared__ __align__(16) __half sh[];
    const uint32_t sb = smem_u32(sh);

    const int tid = threadIdx.x, lane = tid & 31, wid = tid >> 5;
    const int g = lane >> 2, tq2 = (lane & 3) << 1;
    const int wr = wid << 5;
    const int bh = blockIdx.y, q0 = blockIdx.x << 7, sp = blockIdx.z;
    const int t0 = sp * kTilesPerSplit;

    const __half* Qg = g_qh + ((size_t)bh * kNQ + q0) * kHD;
    const __half* Kg = g_kh + (size_t)bh * kNC * kHD + (size_t)t0 * 64 * kHD;
    const __half* Vg = g_vh + (size_t)bh * kNC * kHD + (size_t)t0 * 64 * kHD;

    const int qrow_l = (lane & 7) + ((lane >> 3) & 1) * 8;   // V rows (trans ldsm)
    const int qcol_l = ((lane >> 4) & 1) * 8;
    const int krow_l = (lane & 7) + ((lane >> 4) & 1) * 8;   // K (B) n-rows
    const int kcol_l = ((lane >> 3) & 1) * 8;

    // Stage K/V tile 0
#pragma unroll
    for (int p = 0; p < 4; p++) {
        int c = tid + (p << 7);
        int row = c >> 3, seg = (c & 7) << 3;
        CP16(sb + 2 * (H_K0 + row * 72 + seg), Kg + (row << 6) + seg);
        CP16(sb + 2 * (H_V0 + row * 72 + seg), Vg + (row << 6) + seg);
    }
    CP_COMMIT();

    // Q fragments straight from gmem
    uint32_t qa[2][4][4];
#pragma unroll
    for (int mf = 0; mf < 2; mf++)
#pragma unroll
        for (int kc = 0; kc < 4; kc++) {
            const __half* qp = Qg + (wr + (mf << 4) + g) * kHD + (kc << 4) + tq2;
            qa[mf][kc][0] = *(const uint32_t*)qp;
            qa[mf][kc][1] = *(const uint32_t*)(qp + 8 * kHD);
            qa[mf][kc][2] = *(const uint32_t*)(qp + 8);
            qa[mf][kc][3] = *(const uint32_t*)(qp + 8 * kHD + 8);
        }

    float o[2][8][4] = {};
    float l32[2][2] = {};   // [mf][row-class g / g+8]

    CP_WAIT0();
    __syncthreads();

    for (int tk = 0; tk < kTilesPerSplit; tk++) {
        const int cur = tk & 1;
        if (tk < kTilesPerSplit - 1) {
            const __half* Kt = Kg + (size_t)(tk + 1) * 64 * kHD;
            const __half* Vt = Vg + (size_t)(tk + 1) * 64 * kHD;
            const int kd = cur ? H_K0 : H_K1;
            const int vd = cur ? H_V0 : H_V1;
#pragma unroll
            for (int p = 0; p < 4; p++) {
                int c = tid + (p << 7);
                int row = c >> 3, seg = (c & 7) << 3;
                CP16(sb + 2 * (kd + row * 72 + seg), Kt + (row << 6) + seg);
                CP16(sb + 2 * (vd + row * 72 + seg), Vt + (row << 6) + seg);
            }
            CP_COMMIT();
        }
        const uint32_t kbase = sb + 2 * (cur ? H_K1 : H_K0);
        const uint32_t vbase = sb + 2 * (cur ? H_V1 : H_V0);

        // ---- Phase 1: S = Q.K^T (fp16 acc) for ALL 4 np chunks ----
        uint32_t s[4][2][4] = {};
#pragma unroll
        for (int np = 0; np < 4; np++) {
#pragma unroll
            for (int kc = 0; kc < 4; kc++) {
                uint32_t kb[4];
                LDSM4(kb, kbase + 2 * (((np << 4) + krow_l) * 72 + (kc << 4) + kcol_l));
                mma_f16acc(&s[np][0][0], qa[0][kc], kb[0], kb[1]);
                mma_f16acc(&s[np][1][0], qa[1][kc], kb[0], kb[1]);
                mma_f16acc(&s[np][0][2], qa[0][kc], kb[2], kb[3]);
                mma_f16acc(&s[np][1][2], qa[1][kc], kb[2], kb[3]);
            }
        }

        // ---- Phase 2: exp2 in place (s -> p, A-frag order already) ----
#pragma unroll
        for (int np = 0; np < 4; np++)
#pragma unroll
            for (int mf = 0; mf < 2; mf++) {
                s[np][mf][0] = ex2u(s[np][mf][0]);
                s[np][mf][1] = ex2u(s[np][mf][1]);
                s[np][mf][2] = ex2u(s[np][mf][2]);
                s[np][mf][3] = ex2u(s[np][mf][3]);
            }

        // ---- l: HADD2 trees over P frags (regs 0,2 = row g; 1,3 = row g+8) ----
#pragma unroll
        for (int mf = 0; mf < 2; mf++) {
            uint32_t hg  = hadd2u(hadd2u(s[0][mf][0], s[0][mf][2]),
                                  hadd2u(s[1][mf][0], s[1][mf][2]));
            hg = hadd2u(hg, hadd2u(hadd2u(s[2][mf][0], s[2][mf][2]),
                                   hadd2u(s[3][mf][0], s[3][mf][2])));
            uint32_t hg8 = hadd2u(hadd2u(s[0][mf][1], s[0][mf][3]),
                                  hadd2u(s[1][mf][1], s[1][mf][3]));
            hg8 = hadd2u(hg8, hadd2u(hadd2u(s[2][mf][1], s[2][mf][3]),
                                     hadd2u(s[3][mf][1], s[3][mf][3])));
            float2 f0 = __half22float2(*(__half2*)&hg);
            float2 f1 = __half22float2(*(__half2*)&hg8);
            l32[mf][0] += f0.x + f0.y;
            l32[mf][1] += f1.x + f1.y;
        }

        // ---- Phase 3: O += P.V for ALL 4 np chunks ----
#pragma unroll
        for (int np = 0; np < 4; np++) {
#pragma unroll
            for (int vc = 0; vc < 4; vc++) {
                uint32_t vb[4];
                LDSM4T(vb, vbase + 2 * (((np << 4) + qrow_l) * 72 + (vc << 4) + qcol_l));
                mma_f16(o[0][(vc << 1) + 0], s[np][0], vb[0], vb[1]);
                mma_f16(o[1][(vc << 1) + 0], s[np][1], vb[0], vb[1]);
                mma_f16(o[0][(vc << 1) + 1], s[np][0], vb[2], vb[3]);
                mma_f16(o[1][(vc << 1) + 1], s[np][1], vb[2], vb[3]);
            }
        }

        if (tk < kTilesPerSplit - 1) {
            CP_WAIT0();
            __syncthreads();
        }
    }

    // reduce l over the 4 t-lanes sharing each row
#pragma unroll
    for (int mf = 0; mf < 2; mf++)
#pragma unroll
        for (int rc = 0; rc < 2; rc++) {
            l32[mf][rc] += __shfl_xor_sync(0xffffffffu, l32[mf][rc], 1);
            l32[mf][rc] += __shfl_xor_sync(0xffffffffu, l32[mf][rc], 2);
        }

    // store unnormalized partials
    float* pbase = g_po + ((size_t)sp * kRows + (size_t)bh * kNQ + q0) * kHD;
#pragma unroll
    for (int mf = 0; mf < 2; mf++) {
        const int r0 = wr + (mf << 4) + g;
        float* rp = pbase + r0 * kHD;
#pragma unroll
        for (int nf = 0; nf < 8; nf++) {
            const int d = (nf << 3) + tq2;
            *(float2*)(rp + d) = make_float2(o[mf][nf][0], o[mf][nf][1]);
            *(float2*)(rp + 8 * kHD + d) = make_float2(o[mf][nf][2], o[mf][nf][3]);
        }
        if ((lane & 3) == 0) {
            g_pl[(size_t)sp * kRows + (size_t)bh * kNQ + q0 + r0] = l32[mf][0];
            g_pl[(size_t)sp * kRows + (size_t)bh * kNQ + q0 + r0 + 8] = l32[mf][1];
        }
    }
}

// ---------------------------------------------------------------------------
// Combine: sum split partials, normalize, write fp16 g_oh [b,nq,h*64+d]
// ---------------------------------------------------------------------------
__global__ __launch_bounds__(256) void combine_kernel()
{
    const int idx = blockIdx.x * 256 + threadIdx.x;
    const int row = idx >> 4;
    const int d4 = (idx & 15) << 2;

    float4 acc = make_float4(0.f, 0.f, 0.f, 0.f);
    float l = 0.f;
#pragma unroll
    for (int s = 0; s < kSplits; s++) {
        const float4 v = *(const float4*)(g_po + ((size_t)s * kRows + row) * kHD + d4);
        acc.x += v.x; acc.y += v.y; acc.z += v.z; acc.w += v.w;
        l += g_pl[(size_t)s * kRows + row];
    }
    const float inv = 1.0f / l;
    const int bh = row >> 10, iq = row & 1023;
    const int b = bh >> 3, h = bh & 7;
    __half2 h0 = __floats2half2_rn(acc.x * inv, acc.y * inv);
    __half2 h1 = __floats2half2_rn(acc.z * inv, acc.w * inv);
    __half* dst = g_oh + ((size_t)(b * kNQ) + iq) * kD + (h << 6) + d4;
    uint2 u;
    u.x = *(uint32_t*)&h0; u.y = *(uint32_t*)&h1;
    *(uint2*)dst = u;
}

// ---------------------------------------------------------------------------
extern "C" void kernel_launch(void* const* d_in, const int* in_sizes, int n_in,
                              void* d_out, int out_size)
{
    const float* x    = (const float*)d_in[0];
    const float* ctx  = (const float*)d_in[1];
    const float* Wq   = (const float*)d_in[2];
    const float* Wkv  = (const float*)d_in[3];
    const float* Wout = (const float*)d_in[4];
    const float* bout = (const float*)d_in[5];
    float* out = (float*)d_out;

    cudaFuncSetAttribute(attn_mma, cudaFuncAttributeMaxDynamicSharedMemorySize, AT_SMEM);

    // resolve device-global addresses (NEVER pass __device__ symbols from host!)
    __half *xh, *ctxh, *wqh, *wkvh, *wouth, *oh;
    cudaGetSymbolAddress((void**)&xh,    g_xh);
    cudaGetSymbolAddress((void**)&ctxh,  g_ctxh);
    cudaGetSymbolAddress((void**)&wqh,   g_wqh);
    cudaGetSymbolAddress((void**)&wkvh,  g_wkvh);
    cudaGetSymbolAddress((void**)&wouth, g_wouth);
    cudaGetSymbolAddress((void**)&oh,    g_oh);

    // fp32 -> fp16 pre-conversion (once; removes all cvt from gemm hot loops)
    cvt_f2h<<<(kB * kNQ * kD / 8 + 255) / 256, 256>>>(x, xh, kB * kNQ * kD / 8);
    cvt_f2h<<<(kB * kNC * kD / 8 + 255) / 256, 256>>>(ctx, ctxh, kB * kNC * kD / 8);
    cvt_f2h<<<(kD * kD / 8 + 255) / 256, 256>>>(Wq, wqh, kD * kD / 8);
    cvt_f2h<<<(kD * 2 * kD / 8 + 255) / 256, 256>>>(Wkv, wkvh, kD * 2 * kD / 8);
    cvt_f2h<<<(kD * kD / 8 + 255) / 256, 256>>>(Wout, wouth, kD * kD / 8);

    // q = x @ Wq -> g_qh
    hgemm<0><<<dim3(32, 4), 256>>>(xh, wqh, nullptr, nullptr);
    // kv = ctx @ Wkv -> g_kh, g_vh (n-fastest grid)
    hgemm<1><<<dim3(8, 256), 256>>>(ctxh, wkvh, nullptr, nullptr);
    // flash attention split-KV -> g_po, g_pl
    attn_mma<<<dim3(8, 32, kSplits), 128, AT_SMEM>>>();
    // combine partials -> g_oh
    combine_kernel<<<2048, 256>>>();
    // out = g_oh @ Wout + bout
    hgemm<2><<<dim3(32, 4), 256>>>(oh, wouth, bout, out);
}